// round 2
// baseline (speedup 1.0000x reference)
#include <cuda_runtime.h>
#include <cuda_bf16.h>

#define RADIUS   64
#define PAD_VAL  -1000.0f
#define ROW      4096
#define CHUNK    16
#define NCHUNK   256          // chunks per row = ROW/CHUNK
#define THREADS  512          // 2 rows x 256 chunk-threads
#define NEG_INF  -3.0e38f

// 2 rows per block. Thread group r in {0,1} owns row blockIdx.x*2 + r;
// within a row, thread c owns chunk c (16 consecutive floats).
//
// out[i] = relu( max_{j=1..64}(h[i+j] - j) - h[i] ),  right-padded with -1000.
// Per-chunk local reindex g[q] = h[chunk*16+q] - q keeps magnitudes small:
//   W(p) = max( suf_c(p+1), M_{c+1}-16, M_{c+2}-32, M_{c+3}-48, pre_{c+4}(p)-64 )
//   out  = relu(W - g[p])          (the +p and -p cancel exactly)
// suf is a running scalar in a descending loop -> no suf[] array, no x[] array.
__global__ __launch_bounds__(THREADS, 4) void h2i_kernel(
    const float* __restrict__ hf, float* __restrict__ out)
{
    const int r   = threadIdx.x >> 8;            // row-within-block (0/1)
    const int c   = threadIdx.x & 255;           // chunk id within row
    const int row = (blockIdx.x << 1) | r;

    const float* rp = hf  + (size_t)row * ROW;
    float*       op = out + (size_t)row * ROW;

    // per-row prefix arrays (+4 pad chunks), stride 17 kills bank conflicts
    __shared__ float s_pre[2][NCHUNK + 4][17];
    __shared__ float s_M  [2][NCHUNK + 4];

    // ---- load 16 floats (4x LDG.128) and reindex: g[q] = x[q] - q ----
    float g[16];
    const float4* p4 = (const float4*)(rp + c * CHUNK);
    #pragma unroll
    for (int v = 0; v < 4; v++) {
        float4 t = p4[v];
        g[4*v+0] = t.x - (float)(4*v+0);
        g[4*v+1] = t.y - (float)(4*v+1);
        g[4*v+2] = t.z - (float)(4*v+2);
        g[4*v+3] = t.w - (float)(4*v+3);
    }

    // ---- prefix maxes straight to shared; chunk max M = pre[15] ----
    {
        float pre = g[0];
        s_pre[r][c][0] = pre;
        #pragma unroll
        for (int q = 1; q < 16; q++) { pre = fmaxf(pre, g[q]); s_pre[r][c][q] = pre; }
        s_M[r][c] = pre;
    }

    // ---- pad chunks [4096,4160): h = PAD => g[q] = PAD-q, prefix max = PAD ----
    if (c < 4) {
        s_M[r][NCHUNK + c] = PAD_VAL;
        #pragma unroll
        for (int q = 0; q < 16; q++) s_pre[r][NCHUNK + c][q] = PAD_VAL;
    }
    __syncthreads();

    // ---- chunks c+1..c+3 are fully inside every window of this chunk ----
    const float mid = fmaxf(fmaxf(s_M[r][c + 1] - 16.0f,
                                  s_M[r][c + 2] - 32.0f),
                                  s_M[r][c + 3] - 48.0f);

    // ---- descending combine with running suffix max (no suf[] array) ----
    float res[16];
    float s = NEG_INF;                            // s = max g[p+1..15]
    #pragma unroll
    for (int p = 15; p >= 0; p--) {
        float w = fmaxf(fmaxf(s, mid), s_pre[r][c + 4][p] - 64.0f);
        res[p] = fmaxf(w - g[p], 0.0f);
        s = fmaxf(s, g[p]);
    }

    // ---- store (4x STG.128) ----
    float4* o4 = (float4*)(op + c * CHUNK);
    #pragma unroll
    for (int v = 0; v < 4; v++)
        o4[v] = make_float4(res[4*v+0], res[4*v+1], res[4*v+2], res[4*v+3]);
}

extern "C" void kernel_launch(void* const* d_in, const int* in_sizes, int n_in,
                              void* d_out, int out_size)
{
    const float* hf  = (const float*)d_in[0];
    float*       out = (float*)d_out;
    const int rows = in_sizes[0] / ROW;          // 1024
    (void)n_in; (void)out_size;
    h2i_kernel<<<rows / 2, THREADS>>>(hf, out);
}

// round 3
// speedup vs baseline: 1.4521x; 1.4521x over previous
#include <cuda_runtime.h>
#include <cuda_bf16.h>
#include <cstdio>

#define RADIUS   64
#define PAD_VAL  -1000.0f
#define ROW      4096
#define NROWS    1024
#define CHUNK    16
#define NCHUNK   256          // chunks per row = ROW/CHUNK
#define THREADS  256
#define NEG_INF  -3.0e38f

// One block per row, thread c owns chunk c (16 floats).
// out[i] = relu( max_{j=1..64}(h[i+j] - j) - h[i] ),  right-pad -1000.
// Local reindex g[q] = h[16c+q] - q  (small magnitudes; exact +p/-p cancel):
//   out[p] = relu( max( suf_c(p+1),
//                       M_{c+1}-16, M_{c+2}-32, M_{c+3}-48,
//                       pre_{c+4}(p)-64 ) - g[p] )
// s_pre[c][q] = prefix max of chunk c; M_c = s_pre[c][15]. Stride 17 -> all
// scalar accesses bank-conflict-free. 7 blocks/SM -> single wave of 1024.
__global__ __launch_bounds__(THREADS, 7) void h2i_kernel(
    const float* __restrict__ hf, float* __restrict__ out)
{
    const int c   = threadIdx.x;                 // chunk id within row
    const int row = blockIdx.x;
    const float* rp = hf  + (size_t)row * ROW;
    float*       op = out + (size_t)row * ROW;

    __shared__ float s_pre[NCHUNK + 4][17];      // 17.3 KB

    // ---- load 16 floats (4x LDG.128, front-batched) and reindex ----
    float g[16];
    const float4* p4 = (const float4*)(rp + c * CHUNK);
    #pragma unroll
    for (int v = 0; v < 4; v++) {
        float4 t = p4[v];
        g[4*v+0] = t.x - (float)(4*v+0);
        g[4*v+1] = t.y - (float)(4*v+1);
        g[4*v+2] = t.z - (float)(4*v+2);
        g[4*v+3] = t.w - (float)(4*v+3);
    }

    // ---- prefix maxes straight to shared (chunk max = [15]) ----
    {
        float pre = g[0];
        s_pre[c][0] = pre;
        #pragma unroll
        for (int q = 1; q < 16; q++) { pre = fmaxf(pre, g[q]); s_pre[c][q] = pre; }
    }

    // ---- pad chunks [4096,4160): h = PAD => prefix max = PAD ----
    if (c < 4) {
        #pragma unroll
        for (int q = 0; q < 16; q++) s_pre[NCHUNK + c][q] = PAD_VAL;
    }
    __syncthreads();

    // ---- chunks c+1..c+3 fully inside every window of this chunk ----
    const float mid = fmaxf(fmaxf(s_pre[c + 1][15] - 16.0f,
                                  s_pre[c + 2][15] - 32.0f),
                                  s_pre[c + 3][15] - 48.0f);

    // ---- descending combine, running suffix max, results overwrite g ----
    float s = NEG_INF;                            // s = max g[p+1..15]
    #pragma unroll
    for (int p = 15; p >= 0; p--) {
        float w = fmaxf(fmaxf(s, mid), s_pre[c + 4][p] - 64.0f);
        float gp = g[p];
        s = fmaxf(s, gp);
        g[p] = fmaxf(w - gp, 0.0f);
    }

    // ---- store (4x STG.128) ----
    float4* o4 = (float4*)(op + c * CHUNK);
    #pragma unroll
    for (int v = 0; v < 4; v++)
        o4[v] = make_float4(g[4*v+0], g[4*v+1], g[4*v+2], g[4*v+3]);
}

extern "C" void kernel_launch(void* const* d_in, const int* in_sizes, int n_in,
                              void* d_out, int out_size)
{
    const float* hf  = (const float*)d_in[0];
    float*       out = (float*)d_out;
    (void)in_sizes; (void)n_in; (void)out_size;
    // Ask for max shared-memory carveout so 7 blocks x 17.3KB fit per SM.
    // Host-side attribute set: not a stream op, graph-capture safe, idempotent.
    cudaFuncSetAttribute(h2i_kernel,
                         cudaFuncAttributePreferredSharedMemoryCarveout,
                         cudaSharedmemCarveoutMaxShared);
    h2i_kernel<<<NROWS, THREADS>>>(hf, out);
}

// round 4
// speedup vs baseline: 1.7642x; 1.2149x over previous
#include <cuda_runtime.h>
#include <cuda_bf16.h>

#define RADIUS    64
#define PAD_VAL   -1000.0f
#define ROW       4096
#define NROWS     1024
#define CHUNK     16
#define NCHUNK    256          // chunks per row
#define SEG       28           // output chunks per warp (lanes 28-31 = halo)
#define WPR       10           // warps per row: ceil(256/28)
#define THREADS   256          // 8 independent warps per block, NO syncthreads
#define NEG_INF   -3.0e38f

// out[i] = relu( max_{j=1..64}(h[i+j]-j) - h[i] ),  right-pad -1000.
// Lane owns chunk c (16 floats), local reindex g[q] = h[16c+q] - q:
//   out[p] = relu( max( suf_c(p+1), M_{c+1}-16, M_{c+2}-32, M_{c+3}-48,
//                       pre_{c+4}(p)-64 ) - g[p] )
// Cross-chunk terms come from lanes c+1..c+4 via __shfl_down_sync — no shared
// memory, no barriers. Warp covers 32 consecutive chunks, stores first 28.
__global__ __launch_bounds__(THREADS, 5) void h2i_kernel(
    const float* __restrict__ hf, float* __restrict__ out)
{
    const int lane = threadIdx.x & 31;
    const int wid  = (blockIdx.x << 3) | (threadIdx.x >> 5);  // global warp id
    const int row  = wid / WPR;
    const int seg  = wid - row * WPR;
    const int c    = seg * SEG + lane;           // chunk id, in [0, 280)

    float g[16], pre[16];

    if (c < NCHUNK) {
        // ---- load 16 floats (4x LDG.128) and reindex g[q] = x[q] - q ----
        const float4* p4 = (const float4*)(hf + (size_t)row * ROW + c * CHUNK);
        #pragma unroll
        for (int v = 0; v < 4; v++) {
            float4 t = p4[v];
            g[4*v+0] = t.x - (float)(4*v+0);
            g[4*v+1] = t.y - (float)(4*v+1);
            g[4*v+2] = t.z - (float)(4*v+2);
            g[4*v+3] = t.w - (float)(4*v+3);
        }
        // ---- prefix maxes (chunk max = pre[15]) ----
        pre[0] = g[0];
        #pragma unroll
        for (int q = 1; q < 16; q++) pre[q] = fmaxf(pre[q-1], g[q]);
    } else {
        // pad chunks: h = PAD everywhere -> g[q] = PAD - q, prefix max = PAD
        #pragma unroll
        for (int q = 0; q < 16; q++) { g[q] = PAD_VAL - (float)q; pre[q] = PAD_VAL; }
    }

    // ---- chunk maxes of c+1..c+3 (fully inside every window of chunk c) ----
    const float m1 = __shfl_down_sync(0xffffffffu, pre[15], 1);
    const float m2 = __shfl_down_sync(0xffffffffu, pre[15], 2);
    const float m3 = __shfl_down_sync(0xffffffffu, pre[15], 3);
    const float mid = fmaxf(fmaxf(m1 - 16.0f, m2 - 32.0f), m3 - 48.0f);

    // ---- descending combine with running suffix max; prefix of chunk c+4
    //      fetched per-element via shuffle (results only valid for lane < 28) ----
    float s = NEG_INF;                            // s = max g[p+1..15]
    #pragma unroll
    for (int p = 15; p >= 0; p--) {
        float p4v = __shfl_down_sync(0xffffffffu, pre[p], 4) - 64.0f;
        float w   = fmaxf(fmaxf(s, mid), p4v);
        float gp  = g[p];
        s = fmaxf(s, gp);
        g[p] = fmaxf(w - gp, 0.0f);
    }

    // ---- store (4x STG.128); halo lanes and pad chunks store nothing ----
    if (lane < SEG && c < NCHUNK) {
        float4* o4 = (float4*)(out + (size_t)row * ROW + c * CHUNK);
        #pragma unroll
        for (int v = 0; v < 4; v++)
            o4[v] = make_float4(g[4*v+0], g[4*v+1], g[4*v+2], g[4*v+3]);
    }
}

extern "C" void kernel_launch(void* const* d_in, const int* in_sizes, int n_in,
                              void* d_out, int out_size)
{
    const float* hf  = (const float*)d_in[0];
    float*       out = (float*)d_out;
    (void)in_sizes; (void)n_in; (void)out_size;
    // grid: 1024 rows x 10 warps / 8 warps per block = 1280 blocks (exact)
    h2i_kernel<<<NROWS * WPR / 8, THREADS>>>(hf, out);
}